// round 4
// baseline (speedup 1.0000x reference)
#include <cuda_runtime.h>
#include <cstdint>

// SpottingLoss: greedy bipartite matching (2 phases) + YOLO-style loss.
// B=2048 batches, N=64 slots, F=19 features.
// Round 3: warp-per-batch (2 rows/lane), rescan-only-on-conflict,
//          __syncwarp instead of block barriers.

#define N_ 64
#define F_ 19
#define BPB 4                 // batches (warps) per 128-thread block
#define LAMBDA_COORD 5.0f
#define LAMBDA_NOOBJ 0.5f
#define FULLM 0xFFFFFFFFu

__global__ void zero_kernel(float* out, int n) {
    int i = blockIdx.x * blockDim.x + threadIdx.x;
    if (i < n) out[i] = 0.0f;
}

// First-index argmax of D1[i,j] = 1-|x-p[j]| over free columns (ascending j,
// strict > keeps the lowest index on ties — JAX argmax semantics).
__device__ __forceinline__ void scan_row(unsigned long long fm, float x,
                                         const float* __restrict__ p,
                                         float& bv, int& bj)
{
    bv = -1.0f; bj = 0;
    while (fm) {
        int j = __ffsll((long long)fm) - 1;
        fm &= fm - 1;
        float v = 1.0f - fabsf(x - p[j]);
        if (v > bv) { bv = v; bj = j; }
    }
}

// Column-acceptance key: (value bits << 32) | ~row. Values are >= 0 so float
// bits are monotone; larger key = larger value, then lower row index —
// exactly the reference's argmax-over-rows tie-breaking.
__device__ __forceinline__ unsigned long long mk_key(float v, int row) {
    return ((unsigned long long)__float_as_uint(v) << 32) |
           (unsigned long long)(FULLM - (unsigned)row);
}

__global__ __launch_bounds__(32 * BPB) void spotting_loss_kernel(
    const float* __restrict__ y_true,
    const float* __restrict__ y_pred,
    float* __restrict__ out,
    int batches)
{
    __shared__ float p_s[BPB][N_];
    __shared__ unsigned long long colkey[BPB][N_];
    __shared__ unsigned long long freemask[BPB];

    const int w    = threadIdx.x >> 5;          // warp = batch slot in block
    const int lane = threadIdx.x & 31;
    const int b    = blockIdx.x * BPB + w;
    if (b >= batches) return;

    const float* gt = y_true + (size_t)b * (N_ * F_);
    const float* gp = y_pred + (size_t)b * (N_ * F_);

    const int r0 = lane, r1 = lane + 32;

    // Stage p[j] = y_pred[j][1]; init per-warp matching state.
    p_s[w][r0] = __ldg(gp + r0 * F_ + 1);
    p_s[w][r1] = __ldg(gp + r1 * F_ + 1);
    colkey[w][r0] = 0ull;
    colkey[w][r1] = 0ull;
    if (lane == 0) freemask[w] = ~0ull;

    const float a0 = __ldg(gt + r0 * F_ + 0);   // exactly 0.0f or 1.0f
    const float a1 = __ldg(gt + r1 * F_ + 0);
    const float x0 = __ldg(gt + r0 * F_ + 1);
    const float x1 = __ldg(gt + r1 * F_ + 1);

    int   perm0 = 0, perm1 = 0;
    float bv0 = -1.0f, bv1 = -1.0f;
    int   bj0 = 0, bj1 = 0;

    __syncwarp();

    // Phase 0: rows with alpha==1; phase 1: rows with alpha==0 vs leftover cols.
    for (int phase = 0; phase < 2; ++phase) {
        bool act0 = (phase == 0) ? (a0 > 0.5f) : (a0 <= 0.5f);
        bool act1 = (phase == 0) ? (a1 > 0.5f) : (a1 <= 0.5f);
        bool need0 = act0, need1 = act1;       // full scan at phase start

        for (int it = 0; it < N_; ++it) {
            if (!__ballot_sync(FULLM, act0 | act1)) break;

            // Rescan only if this row's target column was taken (or phase start).
            unsigned long long fm = freemask[w];
            if (act0 & need0) { scan_row(fm, x0, p_s[w], bv0, bj0); need0 = false; }
            if (act1 & need1) { scan_row(fm, x1, p_s[w], bv1, bj1); need1 = false; }

            if (act0) atomicMax(&colkey[w][bj0], mk_key(bv0, r0));
            if (act1) atomicMax(&colkey[w][bj1], mk_key(bv1, r1));
            __syncwarp();                       // proposals visible

            bool win0 = act0 &&
                ((unsigned)(colkey[w][bj0] & 0xFFFFFFFFull) == FULLM - (unsigned)r0);
            bool win1 = act1 &&
                ((unsigned)(colkey[w][bj1] & 0xFFFFFFFFull) == FULLM - (unsigned)r1);

            unsigned long long clear = 0;
            if (win0) clear |= 1ull << bj0;
            if (win1) clear |= 1ull << bj1;
            if (clear) atomicAnd(&freemask[w], ~clear);
            __syncwarp();                       // colkey reads + mask updates done

            if (win0) { act0 = false; perm0 = bj0; }
            if (win1) { act1 = false; perm1 = bj1; }

            unsigned long long fm2 = freemask[w];
            if (act0) need0 = !((fm2 >> bj0) & 1);   // lost a conflict -> rescan
            if (act1) need1 = !((fm2 >> bj1) & 1);

            colkey[w][r0] = 0ull;               // reset for next round
            colkey[w][r1] = 0ull;
            __syncwarp();                       // resets ordered before proposals
        }
    }

    // Loss for both rows using permuted prediction rows perm0/perm1.
    float acc = 0.0f;
#pragma unroll
    for (int h = 0; h < 2; ++h) {
        const int   r    = h ? r1 : r0;
        const int   perm = h ? perm1 : perm0;
        const float a    = h ? a1 : a0;
        const float x    = h ? x1 : x0;
        const float* gtr = gt + r * F_;
        const float* ypr = gp + perm * F_;
        float d0  = a - __ldg(ypr + 0);
        float dxv = x - __ldg(ypr + 1);
        float s = 0.0f;
#pragma unroll
        for (int f = 2; f < F_; ++f) {
            float d = __ldg(gtr + f) - __ldg(ypr + f);
            s += d * d;
        }
        acc += a * (LAMBDA_COORD * dxv * dxv + d0 * d0 + s)
             + (1.0f - a) * (LAMBDA_NOOBJ * d0 * d0);
    }

    // Warp reduction, one atomicAdd per batch.
#pragma unroll
    for (int o = 16; o; o >>= 1) acc += __shfl_down_sync(FULLM, acc, o);
    if (lane == 0) atomicAdd(out, acc);
}

extern "C" void kernel_launch(void* const* d_in, const int* in_sizes, int n_in,
                              void* d_out, int out_size)
{
    const float* y_true = (const float*)d_in[0];
    const float* y_pred = (const float*)d_in[1];
    float* out = (float*)d_out;

    zero_kernel<<<(out_size + 255) / 256, 256>>>(out, out_size);

    int batches = in_sizes[0] / (N_ * F_);               // 2048
    int grid = (batches + BPB - 1) / BPB;                // 512
    spotting_loss_kernel<<<grid, 32 * BPB>>>(y_true, y_pred, out, batches);
}

// round 5
// speedup vs baseline: 2.2754x; 2.2754x over previous
#include <cuda_runtime.h>
#include <cstdint>

// SpottingLoss: greedy bipartite matching (2 phases) + YOLO-style loss.
// B=2048 batches, N=64 slots, F=19 features. One 64-thread CTA per batch.
// R4: poison-based free-set (no freemask, no colkey resets, 2 barriers/round),
//     unrolled 8x8 tree argmax (ILP) instead of serial ffs scan,
//     minimal staging (only alpha/x/p), loss epilogue reads global directly.

#define N_ 64
#define F_ 19
#define LAMBDA_COORD 5.0f
#define LAMBDA_NOOBJ 0.5f
#define FULLM 0xFFFFFFFFu

__global__ void zero_kernel(float* out, int n) {
    int i = blockIdx.x * blockDim.x + threadIdx.x;
    if (i < n) out[i] = 0.0f;
}

// Column-acceptance key: (value bits << 32) | ~row. Proposal values are > 0,
// so float bits are monotone; larger key = larger value, then lower row index
// — exactly the reference's argmax-over-rows tie-breaking.
__device__ __forceinline__ unsigned long long mk_key(float v, int row) {
    return ((unsigned long long)__float_as_uint(v) << 32) |
           (unsigned long long)(FULLM - (unsigned)row);
}

__global__ __launch_bounds__(N_) void spotting_loss_kernel(
    const float* __restrict__ y_true,
    const float* __restrict__ y_pred,
    float* __restrict__ out)
{
    // pm[j] = y_pred[j][1] while column j is free; poisoned to 3.0f once
    // matched, so v = 1-|x-pm[j]| goes negative and the column never wins
    // against any free column (whose v > 0). This IS the free-set.
    __shared__ float pm[N_];
    __shared__ unsigned long long colkey[N_];
    __shared__ float red[2];

    const int b   = blockIdx.x;
    const int tid = threadIdx.x;

    const float* gt = y_true + (size_t)b * (N_ * F_);
    const float* gp = y_pred + (size_t)b * (N_ * F_);

    const float alpha = __ldg(gt + tid * F_ + 0);   // exactly 0.0f or 1.0f
    const float x     = __ldg(gt + tid * F_ + 1);
    pm[tid]     = __ldg(gp + tid * F_ + 1);
    colkey[tid] = 0ull;           // init once; never reset (see round invariant)
    __syncthreads();

    int perm = 0;

    // Invariant: every column that receives >= 1 proposal in a round is
    // matched in that round (its accepted row proposed exactly it), so its
    // colkey entry is stale-but-dead and pm poison keeps it unproposed.
    // Hence: no colkey resets, no explicit free mask, 2 barriers per round.
    for (int phase = 0; phase < 2; ++phase) {
        bool active = (phase == 0) ? (alpha > 0.5f) : (alpha <= 0.5f);

        for (;;) {
            if (__syncthreads_count(active) == 0) break;  // barrier A
            // (also orders last round's pm poison writes before this scan)

            int bj = 0;
            if (active) {
                // Two-level argmax over all 64 columns: 8 independent chunk
                // chains (ILP=8), then serial combine. Strict > keeps the
                // lowest index on ties in both levels = JAX argmax semantics.
                float cv[8]; int cj[8];
#pragma unroll
                for (int c = 0; c < 8; ++c) {
                    float bv = -10.0f; int bi = c * 8;
#pragma unroll
                    for (int k = 0; k < 8; ++k) {
                        int j = c * 8 + k;
                        float v = 1.0f - fabsf(x - pm[j]);
                        if (v > bv) { bv = v; bi = j; }
                    }
                    cv[c] = bv; cj[c] = bi;
                }
                float bv = cv[0]; bj = cj[0];
#pragma unroll
                for (int c = 1; c < 8; ++c)
                    if (cv[c] > bv) { bv = cv[c]; bj = cj[c]; }

                atomicMax(&colkey[bj], mk_key(bv, tid));
            }
            __syncthreads();                              // barrier B

            if (active) {
                unsigned wr = FULLM - (unsigned)(colkey[bj] & 0xFFFFFFFFull);
                if (wr == (unsigned)tid) {                // column accepted us
                    perm   = bj;
                    active = false;
                    pm[bj] = 3.0f;    // poison: single writer, ordered by barrier A
                }
            }
        }
    }
    __syncthreads();

    // Loss for row tid with permuted prediction row `perm` (global reads,
    // L2-hot; tiny one-shot traffic).
    const float* gtr = gt + tid * F_;
    const float* ypr = gp + perm * F_;
    const float a  = alpha;
    const float d0 = a - __ldg(ypr + 0);
    const float dx = x - __ldg(ypr + 1);
    float s = 0.0f;
#pragma unroll
    for (int f = 2; f < F_; ++f) {
        float d = __ldg(gtr + f) - __ldg(ypr + f);
        s += d * d;
    }
    float term = a * (LAMBDA_COORD * dx * dx + d0 * d0 + s)
               + (1.0f - a) * (LAMBDA_NOOBJ * d0 * d0);

    // Block reduction (2 warps), one atomicAdd per batch.
#pragma unroll
    for (int o = 16; o; o >>= 1) term += __shfl_down_sync(FULLM, term, o);
    if ((tid & 31) == 0) red[tid >> 5] = term;
    __syncthreads();
    if (tid == 0) atomicAdd(out, red[0] + red[1]);
}

extern "C" void kernel_launch(void* const* d_in, const int* in_sizes, int n_in,
                              void* d_out, int out_size)
{
    const float* y_true = (const float*)d_in[0];
    const float* y_pred = (const float*)d_in[1];
    float* out = (float*)d_out;

    zero_kernel<<<(out_size + 255) / 256, 256>>>(out, out_size);

    int batches = in_sizes[0] / (N_ * F_);   // 2048
    spotting_loss_kernel<<<batches, N_>>>(y_true, y_pred, out);
}

// round 6
// speedup vs baseline: 5.3333x; 2.3439x over previous
#include <cuda_runtime.h>
#include <cstdint>

// SpottingLoss: greedy bipartite matching + YOLO-style loss.
// B=2048 batches, N=64 slots, F=19 features. One 64-thread CTA per batch.
// R5: PHASE 1 ELIMINATED. The matching is a full permutation; alpha=0 rows'
//     loss depends only on the SET of columns not taken in phase 0
//     (term = 0.5*yp[j,0]^2 per leftover column), not on their assignment.
//     So we run only the alpha=1 matching (~30% of rows) and fold the
//     alpha=0 contribution in per-column via the pm-poison flag.

#define N_ 64
#define F_ 19
#define LAMBDA_COORD 5.0f
#define LAMBDA_NOOBJ 0.5f
#define FULLM 0xFFFFFFFFu

__global__ void zero_kernel(float* out, int n) {
    int i = blockIdx.x * blockDim.x + threadIdx.x;
    if (i < n) out[i] = 0.0f;
}

// Column-acceptance key: (value bits << 32) | ~row. Proposal values are > 0,
// so float bits are monotone; larger key = larger value, then lower row index
// — exactly the reference's argmax-over-rows tie-breaking.
__device__ __forceinline__ unsigned long long mk_key(float v, int row) {
    return ((unsigned long long)__float_as_uint(v) << 32) |
           (unsigned long long)(FULLM - (unsigned)row);
}

__global__ __launch_bounds__(N_) void spotting_loss_kernel(
    const float* __restrict__ y_true,
    const float* __restrict__ y_pred,
    float* __restrict__ out)
{
    // pm[j] = y_pred[j][1] while column j is free; poisoned to 3.0f once
    // matched (v = 1-|x-3| < 0 never beats a free column's v > 0).
    // After matching, pm[j]==3.0f is also the "column taken in phase 0" flag.
    __shared__ float pm[N_];
    __shared__ unsigned long long colkey[N_];
    __shared__ float red[2];

    const int b   = blockIdx.x;
    const int tid = threadIdx.x;

    const float* gt = y_true + (size_t)b * (N_ * F_);
    const float* gp = y_pred + (size_t)b * (N_ * F_);

    const float alpha = __ldg(gt + tid * F_ + 0);   // exactly 0.0f or 1.0f
    const float x     = __ldg(gt + tid * F_ + 1);
    pm[tid]     = __ldg(gp + tid * F_ + 1);
    colkey[tid] = 0ull;           // init once; never reset (round invariant)
    __syncthreads();

    int  perm   = 0;
    bool active = (alpha > 0.5f);                   // phase 0 rows only

    // Invariant: every column proposed in a round is matched in that round,
    // so colkey entries are never reused and pm poison is the only free-set.
    for (;;) {
        if (__syncthreads_count(active) == 0) break;  // barrier A
        // (also orders last round's pm poison writes before this scan)

        int bj = 0;
        if (active) {
            // Two-level argmax over all 64 columns: 8 independent chunk
            // chains (ILP=8), then serial combine. Strict > keeps the
            // lowest index on ties in both levels = JAX argmax semantics.
            float cv[8]; int cj[8];
#pragma unroll
            for (int c = 0; c < 8; ++c) {
                float bv = -10.0f; int bi = c * 8;
#pragma unroll
                for (int k = 0; k < 8; ++k) {
                    int j = c * 8 + k;
                    float v = 1.0f - fabsf(x - pm[j]);
                    if (v > bv) { bv = v; bi = j; }
                }
                cv[c] = bv; cj[c] = bi;
            }
            float bv = cv[0]; bj = cj[0];
#pragma unroll
            for (int c = 1; c < 8; ++c)
                if (cv[c] > bv) { bv = cv[c]; bj = cj[c]; }

            atomicMax(&colkey[bj], mk_key(bv, tid));
        }
        __syncthreads();                              // barrier B

        if (active) {
            unsigned wr = FULLM - (unsigned)(colkey[bj] & 0xFFFFFFFFull);
            if (wr == (unsigned)tid) {                // column accepted us
                perm   = bj;
                active = false;
                pm[bj] = 3.0f;    // poison: single writer, ordered by barrier A
            }
        }
    }
    __syncthreads();   // pm poison flags final before epilogue reads

    float term = 0.0f;

    // alpha=1 row term: full YOLO loss vs permuted prediction row `perm`.
    if (alpha > 0.5f) {
        const float* gtr = gt + tid * F_;
        const float* ypr = gp + perm * F_;
        const float d0 = 1.0f - __ldg(ypr + 0);
        const float dx = x - __ldg(ypr + 1);
        float s = 0.0f;
#pragma unroll
        for (int f = 2; f < F_; ++f) {
            float d = __ldg(gtr + f) - __ldg(ypr + f);
            s += d * d;
        }
        term += LAMBDA_COORD * dx * dx + d0 * d0 + s;
    }

    // alpha=0 contribution, per COLUMN: every column not taken in phase 0 is
    // assigned to exactly one alpha=0 row, contributing 0.5*yp[col,0]^2
    // regardless of which row got it.
    if (pm[tid] != 3.0f) {
        float p0 = __ldg(gp + tid * F_ + 0);
        term += LAMBDA_NOOBJ * p0 * p0;
    }

    // Block reduction (2 warps), one atomicAdd per batch.
#pragma unroll
    for (int o = 16; o; o >>= 1) term += __shfl_down_sync(FULLM, term, o);
    if ((tid & 31) == 0) red[tid >> 5] = term;
    __syncthreads();
    if (tid == 0) atomicAdd(out, red[0] + red[1]);
}

extern "C" void kernel_launch(void* const* d_in, const int* in_sizes, int n_in,
                              void* d_out, int out_size)
{
    const float* y_true = (const float*)d_in[0];
    const float* y_pred = (const float*)d_in[1];
    float* out = (float*)d_out;

    zero_kernel<<<(out_size + 255) / 256, 256>>>(out, out_size);

    int batches = in_sizes[0] / (N_ * F_);   // 2048
    spotting_loss_kernel<<<batches, N_>>>(y_true, y_pred, out);
}